// round 7
// baseline (speedup 1.0000x reference)
#include <cuda_runtime.h>
#include <cuda_bf16.h>
#include <math.h>

// Shapes (fixed dataset):
//   x_all: [100000, 256] f32, n_id: [50000] i32, edge_index: [2, 300000] i32
//   W_sage: [256,256] f32, b_sage: [256] f32, W_cls: [3,256] f32, b_cls: [3] f32
//   out: [50000, 3] f32 (log_softmax)
//
// Algebra: out = log_softmax( mean_j( x[j] @ Wc ) + bc )  (linearity of mean+GEMM)
// Single persistent kernel, 4 phases separated by device-wide barriers:
//   P0: Wc/bc fusion   P1: z[i] = row@Wc (+acc seed)   P2: edge REDG   P3: softmax
#define FDIM 256
#define F4   64
#define CCLS 3
#define GRID 512          // <= 4 blocks/SM on >=128 SMs; co-residency guaranteed
#define BLOCK 256
#define TOT_THREADS (GRID * BLOCK)
#define TOT_WARPS   (TOT_THREADS / 32)

__device__ float  g_Wc [CCLS * FDIM];
__device__ float  g_bc [CCLS];
__device__ float4 g_z  [50000];
__device__ float4 g_acc[50000];

// Device-wide sense barrier. g_cnt self-resets; g_gen is monotone across
// graph replays (wrap-safe via != compare) -> deterministic behavior.
__device__ unsigned g_cnt = 0;
__device__ unsigned g_gen = 0;

__device__ __forceinline__ void gbar(unsigned& mygen) {
    __syncthreads();
    if (threadIdx.x == 0) {
        __threadfence();                       // release prior writes
        unsigned target = mygen + 1;
        if (atomicAdd(&g_cnt, 1u) == GRID - 1) {
            g_cnt = 0;
            __threadfence();
            atomicExch(&g_gen, target);        // release
        } else {
            while (*(volatile unsigned*)&g_gen != target) __nanosleep(20);
        }
        __threadfence();                       // acquire
    }
    __syncthreads();
    mygen += 1;
}

__global__ void __launch_bounds__(BLOCK, 4)
k_all(const float4* __restrict__ x_all4,
      const int*    __restrict__ n_id,
      const int*    __restrict__ src,
      const int*    __restrict__ dst,
      const float*  __restrict__ W_sage,
      const float*  __restrict__ b_sage,
      const float*  __restrict__ W_cls,
      const float*  __restrict__ b_cls,
      float* __restrict__ out, int N, int E) {
    const unsigned full = 0xffffffffu;
    int t    = threadIdx.x;
    int lane = t & 31;
    int gtid = blockIdx.x * BLOCK + t;
    int gw   = gtid >> 5;                       // global warp id
    unsigned mygen = *(volatile unsigned*)&g_gen;  // all reads precede 1st release

    // ---- Phase 0: weight fusion (771 warp tasks over 4096 warps) ----------
    if (gw < CCLS * FDIM) {
        int c = gw >> 8, k = gw & 255;
        const float4* wrow = reinterpret_cast<const float4*>(W_sage + k * FDIM);
        const float4* crow = reinterpret_cast<const float4*>(W_cls  + c * FDIM);
        float4 a0 = __ldg(&wrow[lane]);      float4 b0 = __ldg(&crow[lane]);
        float4 a1 = __ldg(&wrow[lane + 32]); float4 b1 = __ldg(&crow[lane + 32]);
        float s = fmaf(a0.x, b0.x, fmaf(a0.y, b0.y, fmaf(a0.z, b0.z, a0.w * b0.w)))
                + fmaf(a1.x, b1.x, fmaf(a1.y, b1.y, fmaf(a1.z, b1.z, a1.w * b1.w)));
        #pragma unroll
        for (int off = 16; off > 0; off >>= 1) s += __shfl_down_sync(full, s, off);
        if (lane == 0) g_Wc[c * FDIM + k] = s;
    } else if (gw < CCLS * FDIM + CCLS) {
        int c = gw - CCLS * FDIM;
        const float4* brow = reinterpret_cast<const float4*>(b_sage);
        const float4* crow = reinterpret_cast<const float4*>(W_cls + c * FDIM);
        float4 a0 = __ldg(&brow[lane]);      float4 b0 = __ldg(&crow[lane]);
        float4 a1 = __ldg(&brow[lane + 32]); float4 b1 = __ldg(&crow[lane + 32]);
        float s = fmaf(a0.x, b0.x, fmaf(a0.y, b0.y, fmaf(a0.z, b0.z, a0.w * b0.w)))
                + fmaf(a1.x, b1.x, fmaf(a1.y, b1.y, fmaf(a1.z, b1.z, a1.w * b1.w)));
        #pragma unroll
        for (int off = 16; off > 0; off >>= 1) s += __shfl_down_sync(full, s, off);
        if (lane == 0) g_bc[c] = s + __ldg(&b_cls[c]);
    }

    gbar(mygen);

    // ---- Phase 1: projection z[i] = x_all[n_id[i]] @ Wc, seed acc ---------
    __shared__ float sW[CCLS][FDIM];
    for (int idx = t; idx < CCLS * FDIM; idx += BLOCK)
        sW[idx >> 8][idx & 255] = g_Wc[idx];
    __syncthreads();

    int k0 = lane * 4, k1 = (lane + 32) * 4;
    for (int w = gw; w < N; w += TOT_WARPS) {
        int row = __ldg(&n_id[w]);
        const float4* xp = x_all4 + (long long)row * F4;
        float4 a0 = __ldg(&xp[lane]);
        float4 a1 = __ldg(&xp[lane + 32]);
        float s0, s1, s2;
        {
            float t0, t1, t2;
            t0 = fmaf(a0.x, sW[0][k0], fmaf(a0.y, sW[0][k0+1], fmaf(a0.z, sW[0][k0+2], a0.w * sW[0][k0+3])));
            t1 = fmaf(a0.x, sW[1][k0], fmaf(a0.y, sW[1][k0+1], fmaf(a0.z, sW[1][k0+2], a0.w * sW[1][k0+3])));
            t2 = fmaf(a0.x, sW[2][k0], fmaf(a0.y, sW[2][k0+1], fmaf(a0.z, sW[2][k0+2], a0.w * sW[2][k0+3])));
            s0 = fmaf(a1.x, sW[0][k1], fmaf(a1.y, sW[0][k1+1], fmaf(a1.z, sW[0][k1+2], fmaf(a1.w, sW[0][k1+3], t0))));
            s1 = fmaf(a1.x, sW[1][k1], fmaf(a1.y, sW[1][k1+1], fmaf(a1.z, sW[1][k1+2], fmaf(a1.w, sW[1][k1+3], t1))));
            s2 = fmaf(a1.x, sW[2][k1], fmaf(a1.y, sW[2][k1+1], fmaf(a1.z, sW[2][k1+2], fmaf(a1.w, sW[2][k1+3], t2))));
        }
        #pragma unroll
        for (int off = 16; off > 0; off >>= 1) {
            s0 += __shfl_down_sync(full, s0, off);
            s1 += __shfl_down_sync(full, s1, off);
            s2 += __shfl_down_sync(full, s2, off);
        }
        if (lane == 0) {
            float4 zv = make_float4(s0, s1, s2, 1.0f);
            g_z[w]   = zv;
            g_acc[w] = zv;    // self loop (+count)
        }
    }

    gbar(mygen);

    // ---- Phase 2: edge aggregation (2 edges/iter, int2 loads, v4 REDG) ----
    int pairs = (E + 1) >> 1;
    for (int p = gtid; p < pairs; p += TOT_THREADS) {
        int e0 = p * 2;
        if (e0 + 1 < E) {
            int2 sv = __ldg(reinterpret_cast<const int2*>(src) + p);
            int2 dv = __ldg(reinterpret_cast<const int2*>(dst) + p);
            float4 v0 = __ldg(&g_z[sv.x]);
            float4 v1 = __ldg(&g_z[sv.y]);
            asm volatile("red.global.add.v4.f32 [%0], {%1, %2, %3, %4};"
                         :: "l"(&g_acc[dv.x]), "f"(v0.x), "f"(v0.y), "f"(v0.z), "f"(v0.w)
                         : "memory");
            asm volatile("red.global.add.v4.f32 [%0], {%1, %2, %3, %4};"
                         :: "l"(&g_acc[dv.y]), "f"(v1.x), "f"(v1.y), "f"(v1.z), "f"(v1.w)
                         : "memory");
        } else {
            int s = __ldg(&src[e0]);
            int d = __ldg(&dst[e0]);
            float4 v = __ldg(&g_z[s]);
            asm volatile("red.global.add.v4.f32 [%0], {%1, %2, %3, %4};"
                         :: "l"(&g_acc[d]), "f"(v.x), "f"(v.y), "f"(v.z), "f"(v.w)
                         : "memory");
        }
    }

    gbar(mygen);

    // ---- Phase 3: mean + bias + log_softmax ------------------------------
    float bc0 = g_bc[0], bc1 = g_bc[1], bc2 = g_bc[2];
    for (int i = gtid; i < N; i += TOT_THREADS) {
        float4 a = g_acc[i];
        float inv = __frcp_rn(a.w);
        float s0 = fmaf(a.x, inv, bc0);
        float s1 = fmaf(a.y, inv, bc1);
        float s2 = fmaf(a.z, inv, bc2);
        float m   = fmaxf(s0, fmaxf(s1, s2));
        float e0 = __expf(s0 - m);
        float e1 = __expf(s1 - m);
        float e2 = __expf(s2 - m);
        float lse = m + __logf(e0 + e1 + e2);
        out[i * 3 + 0] = s0 - lse;
        out[i * 3 + 1] = s1 - lse;
        out[i * 3 + 2] = s2 - lse;
    }
}

// ---------------------------------------------------------------------------
extern "C" void kernel_launch(void* const* d_in, const int* in_sizes, int n_in,
                              void* d_out, int out_size) {
    const float* x_all  = (const float*)d_in[0];
    const int*   n_id   = (const int*)  d_in[1];
    const int*   eidx   = (const int*)  d_in[2];
    const float* W_sage = (const float*)d_in[3];
    const float* b_sage = (const float*)d_in[4];
    const float* W_cls  = (const float*)d_in[5];
    const float* b_cls  = (const float*)d_in[6];
    float* out = (float*)d_out;

    int N = in_sizes[1];          // 50000
    int E = in_sizes[2] / 2;      // 300000
    const int* src = eidx;        // edge_index[0, :]
    const int* dst = eidx + E;    // edge_index[1, :]

    k_all<<<GRID, BLOCK>>>(reinterpret_cast<const float4*>(x_all), n_id,
                           src, dst, W_sage, b_sage, W_cls, b_cls,
                           out, N, E);
}

// round 8
// speedup vs baseline: 1.2764x; 1.2764x over previous
#include <cuda_runtime.h>
#include <cuda_bf16.h>
#include <math.h>

// Shapes (fixed dataset):
//   x_all: [100000, 256] f32, n_id: [50000] i32, edge_index: [2, 300000] i32
//   W_sage: [256,256] f32, b_sage: [256] f32, W_cls: [3,256] f32, b_cls: [3] f32
//   out: [50000, 3] f32 (log_softmax)
//
// Algebra: out = log_softmax( mean_j( x[j] @ Wc ) + bc )  (linearity)
// 4-kernel pipeline (R5 structure, 25.1us) + PDL edges to hide the ~4us of
// inter-kernel launch overhead: producers signal launch_dependents after
// their stores; consumers griddepcontrol.wait before reading producer data.
#define NMAX 50000
#define FDIM 256
#define F4   64
#define CCLS 3

__device__ float  g_Wc [CCLS * FDIM];
__device__ float  g_bc [CCLS];
__device__ float4 g_z  [NMAX];
__device__ float4 g_acc[NMAX];

__device__ __forceinline__ void pdl_wait()    { asm volatile("griddepcontrol.wait;" ::: "memory"); }
__device__ __forceinline__ void pdl_trigger() { asm volatile("griddepcontrol.launch_dependents;" ::: "memory"); }

// ---------------------------------------------------------------------------
// Kernel 0: parallel weight fusion. One warp per output element.
// ---------------------------------------------------------------------------
__global__ void k_init(const float* __restrict__ W_sage,
                       const float* __restrict__ b_sage,
                       const float* __restrict__ W_cls,
                       const float* __restrict__ b_cls) {
    int gid  = blockIdx.x * blockDim.x + threadIdx.x;
    int ww   = gid >> 5;
    int lane = gid & 31;
    const unsigned full = 0xffffffffu;

    if (ww < CCLS * FDIM) {
        int c = ww >> 8;
        int k = ww & 255;
        const float4* wrow = reinterpret_cast<const float4*>(W_sage + k * FDIM);
        const float4* crow = reinterpret_cast<const float4*>(W_cls  + c * FDIM);
        float4 a0 = __ldg(&wrow[lane]);      float4 b0 = __ldg(&crow[lane]);
        float4 a1 = __ldg(&wrow[lane + 32]); float4 b1 = __ldg(&crow[lane + 32]);
        float s = fmaf(a0.x, b0.x, fmaf(a0.y, b0.y, fmaf(a0.z, b0.z, a0.w * b0.w)))
                + fmaf(a1.x, b1.x, fmaf(a1.y, b1.y, fmaf(a1.z, b1.z, a1.w * b1.w)));
        #pragma unroll
        for (int off = 16; off > 0; off >>= 1)
            s += __shfl_down_sync(full, s, off);
        if (lane == 0) g_Wc[c * FDIM + k] = s;
    } else if (ww < CCLS * FDIM + CCLS) {
        int c = ww - CCLS * FDIM;
        const float4* brow = reinterpret_cast<const float4*>(b_sage);
        const float4* crow = reinterpret_cast<const float4*>(W_cls + c * FDIM);
        float4 a0 = __ldg(&brow[lane]);      float4 b0 = __ldg(&crow[lane]);
        float4 a1 = __ldg(&brow[lane + 32]); float4 b1 = __ldg(&crow[lane + 32]);
        float s = fmaf(a0.x, b0.x, fmaf(a0.y, b0.y, fmaf(a0.z, b0.z, a0.w * b0.w)))
                + fmaf(a1.x, b1.x, fmaf(a1.y, b1.y, fmaf(a1.z, b1.z, a1.w * b1.w)));
        #pragma unroll
        for (int off = 16; off > 0; off >>= 1)
            s += __shfl_down_sync(full, s, off);
        if (lane == 0) g_bc[c] = s + __ldg(&b_cls[c]);
    }
    pdl_trigger();
}

// ---------------------------------------------------------------------------
// Kernel 1: project. One warp per node: z[i] = x_all[n_id[i]] @ Wc, .w = 1.
// Seeds acc[i] = z[i]. Prologue (n_id load + row fetch) runs BEFORE the PDL
// wait -- it depends only on kernel inputs, not on k_init's output.
// ---------------------------------------------------------------------------
__global__ void k_z(const float4* __restrict__ x_all4,
                    const int* __restrict__ n_id, int N) {
    __shared__ float sW[CCLS][FDIM];
    int t    = threadIdx.x;
    int w    = (blockIdx.x * blockDim.x + t) >> 5;
    int lane = t & 31;

    // pre-wait prologue: fetch feature row (independent of g_Wc)
    float4 a0 = make_float4(0.f, 0.f, 0.f, 0.f), a1 = a0;
    if (w < N) {
        int row = __ldg(&n_id[w]);
        const float4* xp = x_all4 + (long long)row * F4;
        a0 = __ldg(&xp[lane]);
        a1 = __ldg(&xp[lane + 32]);
    }

    pdl_wait();   // g_Wc ready beyond this point
    for (int idx = t; idx < CCLS * FDIM; idx += blockDim.x)
        sW[idx >> 8][idx & 255] = g_Wc[idx];
    __syncthreads();

    if (w < N) {
        int k0 = lane * 4, k1 = (lane + 32) * 4;
        float s0, s1, s2;
        {
            float t0, t1, t2;
            t0 = fmaf(a0.x, sW[0][k0], fmaf(a0.y, sW[0][k0+1], fmaf(a0.z, sW[0][k0+2], a0.w * sW[0][k0+3])));
            t1 = fmaf(a0.x, sW[1][k0], fmaf(a0.y, sW[1][k0+1], fmaf(a0.z, sW[1][k0+2], a0.w * sW[1][k0+3])));
            t2 = fmaf(a0.x, sW[2][k0], fmaf(a0.y, sW[2][k0+1], fmaf(a0.z, sW[2][k0+2], a0.w * sW[2][k0+3])));
            s0 = fmaf(a1.x, sW[0][k1], fmaf(a1.y, sW[0][k1+1], fmaf(a1.z, sW[0][k1+2], fmaf(a1.w, sW[0][k1+3], t0))));
            s1 = fmaf(a1.x, sW[1][k1], fmaf(a1.y, sW[1][k1+1], fmaf(a1.z, sW[1][k1+2], fmaf(a1.w, sW[1][k1+3], t1))));
            s2 = fmaf(a1.x, sW[2][k1], fmaf(a1.y, sW[2][k1+1], fmaf(a1.z, sW[2][k1+2], fmaf(a1.w, sW[2][k1+3], t2))));
        }
        const unsigned full = 0xffffffffu;
        #pragma unroll
        for (int off = 16; off > 0; off >>= 1) {
            s0 += __shfl_down_sync(full, s0, off);
            s1 += __shfl_down_sync(full, s1, off);
            s2 += __shfl_down_sync(full, s2, off);
        }
        if (lane == 0) {
            float4 zv = make_float4(s0, s1, s2, 1.0f);
            g_z[w]   = zv;
            g_acc[w] = zv;   // self loop (+count)
        }
    }
    pdl_trigger();
}

// ---------------------------------------------------------------------------
// Kernel 2: edge aggregation over 3-vectors. Two edges per thread.
// Pre-wait prologue: load the edge indices (kernel inputs).
// ---------------------------------------------------------------------------
__global__ void k_edge(const int* __restrict__ src,
                       const int* __restrict__ dst, int E) {
    int p  = blockIdx.x * blockDim.x + threadIdx.x;
    int e0 = p * 2;
    if (e0 >= E) { pdl_wait(); pdl_trigger(); return; }

    if (e0 + 1 < E) {
        int2 sv = __ldg(reinterpret_cast<const int2*>(src) + p);
        int2 dv = __ldg(reinterpret_cast<const int2*>(dst) + p);
        pdl_wait();   // g_z / g_acc ready
        float4 v0 = __ldg(&g_z[sv.x]);
        float4 v1 = __ldg(&g_z[sv.y]);
        asm volatile("red.global.add.v4.f32 [%0], {%1, %2, %3, %4};"
                     :: "l"(&g_acc[dv.x]), "f"(v0.x), "f"(v0.y), "f"(v0.z), "f"(v0.w)
                     : "memory");
        asm volatile("red.global.add.v4.f32 [%0], {%1, %2, %3, %4};"
                     :: "l"(&g_acc[dv.y]), "f"(v1.x), "f"(v1.y), "f"(v1.z), "f"(v1.w)
                     : "memory");
    } else {
        int s = __ldg(&src[e0]);
        int d = __ldg(&dst[e0]);
        pdl_wait();
        float4 v = __ldg(&g_z[s]);
        asm volatile("red.global.add.v4.f32 [%0], {%1, %2, %3, %4};"
                     :: "l"(&g_acc[d]), "f"(v.x), "f"(v.y), "f"(v.z), "f"(v.w)
                     : "memory");
    }
    pdl_trigger();
}

// ---------------------------------------------------------------------------
// Kernel 3: finalize. mean + bias + log_softmax (MUFU intrinsics).
// ---------------------------------------------------------------------------
__global__ void k_final(float* __restrict__ out, int N) {
    int i = blockIdx.x * blockDim.x + threadIdx.x;
    pdl_wait();   // all REDG from k_edge visible
    if (i >= N) return;
    float4 a = g_acc[i];
    float inv = __frcp_rn(a.w);
    float s0 = fmaf(a.x, inv, g_bc[0]);
    float s1 = fmaf(a.y, inv, g_bc[1]);
    float s2 = fmaf(a.z, inv, g_bc[2]);
    float m   = fmaxf(s0, fmaxf(s1, s2));
    float e0 = __expf(s0 - m);
    float e1 = __expf(s1 - m);
    float e2 = __expf(s2 - m);
    float lse = m + __logf(e0 + e1 + e2);
    out[i * 3 + 0] = s0 - lse;
    out[i * 3 + 1] = s1 - lse;
    out[i * 3 + 2] = s2 - lse;
}

// ---------------------------------------------------------------------------
static inline void launch_pdl(void* fn, dim3 grid, dim3 block,
                              void** args, bool pdl_in) {
    cudaLaunchConfig_t cfg = {};
    cfg.gridDim  = grid;
    cfg.blockDim = block;
    cfg.dynamicSmemBytes = 0;
    cfg.stream = 0;
    cudaLaunchAttribute attr[1];
    int nattr = 0;
    if (pdl_in) {
        attr[0].id = cudaLaunchAttributeProgrammaticStreamSerialization;
        attr[0].val.programmaticStreamSerializationAllowed = 1;
        nattr = 1;
    }
    cfg.attrs = attr;
    cfg.numAttrs = nattr;
    cudaLaunchKernelExC(&cfg, fn, args);
}

extern "C" void kernel_launch(void* const* d_in, const int* in_sizes, int n_in,
                              void* d_out, int out_size) {
    const float* x_all  = (const float*)d_in[0];
    const int*   n_id   = (const int*)  d_in[1];
    const int*   eidx   = (const int*)  d_in[2];
    const float* W_sage = (const float*)d_in[3];
    const float* b_sage = (const float*)d_in[4];
    const float* W_cls  = (const float*)d_in[5];
    const float* b_cls  = (const float*)d_in[6];
    float* out = (float*)d_out;

    int N = in_sizes[1];          // 50000
    int E = in_sizes[2] / 2;      // 300000
    const int* src = eidx;        // edge_index[0, :]
    const int* dst = eidx + E;    // edge_index[1, :]

    // k_init: 771 warp-tasks
    {
        int threads = (CCLS * FDIM + CCLS) * 32;
        dim3 g((threads + 255) / 256), b(256);
        void* args[] = {(void*)&W_sage, (void*)&b_sage, (void*)&W_cls, (void*)&b_cls};
        launch_pdl((void*)k_init, g, b, args, false);
    }
    // k_z: one warp per node
    {
        const float4* x4 = reinterpret_cast<const float4*>(x_all);
        long long th = (long long)N * 32;
        dim3 g((unsigned)((th + 255) / 256)), b(256);
        void* args[] = {(void*)&x4, (void*)&n_id, (void*)&N};
        launch_pdl((void*)k_z, g, b, args, true);
    }
    // k_edge: two edges per thread
    {
        int pairs = (E + 1) / 2;
        dim3 g((pairs + 255) / 256), b(256);
        void* args[] = {(void*)&src, (void*)&dst, (void*)&E};
        launch_pdl((void*)k_edge, g, b, args, true);
    }
    // k_final: one thread per node
    {
        dim3 g((N + 255) / 256), b(256);
        void* args[] = {(void*)&out, (void*)&N};
        launch_pdl((void*)k_final, g, b, args, true);
    }
}